// round 14
// baseline (speedup 1.0000x reference)
#include <cuda_runtime.h>
#include <cstdint>

#define B_  4
#define T_  256
#define U_  128
#define EH_ 512
#define PH_ 320
#define JH_ 512
#define NC_ 1025

// ---------------------------------------------------------------------------
// scratch (no cudaMalloc allowed)
// ---------------------------------------------------------------------------
__device__ float g_e[B_ * T_ * JH_];          // [b*T+t][512]
__device__ float g_p[B_ * U_ * JH_];          // [b*U+u][512]
__device__ float g_wp[JH_ * 1024];            // W cols 0..1023: 128 chunks [k32 x n128]
__device__ float g_wl[JH_];                   // W col 1024
__device__ float g_h[(size_t)1024 * 65536];   // H fragment-packed: 268 MB
__device__ float g_d[1024 * 128];             // per-row col-1024 dots

// ---------------------------------------------------------------------------
// helpers
// ---------------------------------------------------------------------------
__device__ __forceinline__ void mma_tf32(float* c, const float4& a, float bx, float by) {
    const unsigned* au = reinterpret_cast<const unsigned*>(&a);
    unsigned b0 = __float_as_uint(bx), b1 = __float_as_uint(by);
    asm volatile(
        "mma.sync.aligned.m16n8k8.row.col.f32.tf32.tf32.f32 "
        "{%0,%1,%2,%3},{%4,%5,%6,%7},{%8,%9},{%0,%1,%2,%3};\n"
        : "+f"(c[0]), "+f"(c[1]), "+f"(c[2]), "+f"(c[3])
        : "r"(au[0]), "r"(au[1]), "r"(au[2]), "r"(au[3]), "r"(b0), "r"(b1));
}
__device__ __forceinline__ void mbar_init(uint32_t mbar, uint32_t count) {
    asm volatile("mbarrier.init.shared.b64 [%0], %1;\n" :: "r"(mbar), "r"(count) : "memory");
}
__device__ __forceinline__ void mbar_expect_tx(uint32_t mbar, uint32_t bytes) {
    asm volatile("mbarrier.arrive.expect_tx.shared.b64 _, [%0], %1;\n"
                 :: "r"(mbar), "r"(bytes) : "memory");
}
__device__ __forceinline__ void mbar_arrive(uint32_t mbar) {
    asm volatile("mbarrier.arrive.release.cta.shared::cta.b64 _, [%0];\n"
                 :: "r"(mbar) : "memory");
}
__device__ __forceinline__ void bulk_g2s(uint32_t dst, const void* src, uint32_t bytes,
                                         uint32_t mbar) {
    asm volatile(
        "cp.async.bulk.shared::cluster.global.mbarrier::complete_tx::bytes "
        "[%0], [%1], %2, [%3];\n"
        :: "r"(dst), "l"(src), "r"(bytes), "r"(mbar) : "memory");
}
__device__ __forceinline__ void mbar_wait(uint32_t mbar, uint32_t parity) {
    uint32_t done;
    asm volatile(
        "{\n\t.reg .pred p;\n\t"
        "mbarrier.try_wait.parity.acquire.cta.shared::cta.b64 p, [%1], %2;\n\t"
        "selp.b32 %0, 1, 0, p;\n\t}"
        : "=r"(done) : "r"(mbar), "r"(parity) : "memory");
    if (!done) {
        asm volatile(
            "{\n\t.reg .pred P1;\n\t"
            "W_%=:\n\t"
            "mbarrier.try_wait.parity.acquire.cta.shared::cta.b64 P1, [%0], %1, 0x989680;\n\t"
            "@P1 bra.uni D_%=;\n\t"
            "bra.uni W_%=;\n\t"
            "D_%=:\n\t}"
            :: "r"(mbar), "r"(parity) : "memory");
    }
}

// ---------------------------------------------------------------------------
// projection: O[row][j] = sum_h X[b][h][t] * W[h][j] + bias[j]
// ---------------------------------------------------------------------------
__global__ void __launch_bounds__(256)
proj_kernel(const float* __restrict__ X, const float* __restrict__ W,
            const float* __restrict__ bias, float* __restrict__ O,
            int L, int H) {
    __shared__ float Xs[16][64];
    __shared__ float Ws[16][64];
    int tid = threadIdx.x;
    int tc = tid & 15, tr = tid >> 4;
    int j0 = blockIdx.x * 64;
    int row0 = blockIdx.y * 64;
    int b = row0 / L;
    int t0 = row0 % L;

    float acc[4][4];
#pragma unroll
    for (int i = 0; i < 4; i++)
#pragma unroll
        for (int j = 0; j < 4; j++) acc[i][j] = 0.f;

    for (int k0 = 0; k0 < H; k0 += 16) {
#pragma unroll
        for (int i = 0; i < 4; i++) {
            int idx = tid + i * 256;
            int ky = idx >> 6, xx = idx & 63;
            Xs[ky][xx] = X[(size_t)(b * H + k0 + ky) * L + t0 + xx];
            Ws[ky][xx] = W[(size_t)(k0 + ky) * JH_ + j0 + xx];
        }
        __syncthreads();
#pragma unroll
        for (int k = 0; k < 16; k++) {
            float a[4], w[4];
#pragma unroll
            for (int i = 0; i < 4; i++) { a[i] = Xs[k][tr * 4 + i]; w[i] = Ws[k][tc * 4 + i]; }
#pragma unroll
            for (int i = 0; i < 4; i++)
#pragma unroll
                for (int j = 0; j < 4; j++) acc[i][j] += a[i] * w[j];
        }
        __syncthreads();
    }
#pragma unroll
    for (int i = 0; i < 4; i++)
#pragma unroll
        for (int j = 0; j < 4; j++) {
            int col = j0 + tc * 4 + j;
            O[(size_t)(row0 + tr * 4 + i) * JH_ + col] = acc[i][j] + bias[col];
        }
}

// ---------------------------------------------------------------------------
// pack W_out: 128 chunks (g = nc*16 + kc) of [k32 x n128] fragment order:
// within-chunk float f bits: reg4[0:2) lane[2:7) nt2[7:10) k8[10:12)
// j = kc*32 + k8*8 + (lane&3) + (reg4&1)*4
// n = nc*128 + nt2*16 + (reg4>>1)*8 + (lane>>2)
// ---------------------------------------------------------------------------
__global__ void pack_kernel(const float* __restrict__ W) {
    int d = blockIdx.x * 256 + threadIdx.x;
    if (d < JH_ * 1024) {
        int f = d & 4095;
        int chunk = d >> 12;
        int kc = chunk & 15, nc = chunk >> 4;
        int reg4 = f & 3;
        int lane = (f >> 2) & 31;
        int nt2  = (f >> 7) & 7;
        int k8   = (f >> 10) & 3;
        int j = kc * 32 + k8 * 8 + (lane & 3) + (reg4 & 1) * 4;
        int n = nc * 128 + nt2 * 16 + (reg4 >> 1) * 8 + (lane >> 2);
        g_wp[d] = W[(size_t)j * NC_ + n];
    }
    if (d < JH_) g_wl[d] = W[(size_t)d * NC_ + 1024];
}

// ---------------------------------------------------------------------------
// build H (unchanged layout from R12): per block 128 rows (16t x 8u), 16
// chunks of [m128 x k32] fragment-packed; col-1024 dot into g_d.
// ---------------------------------------------------------------------------
__global__ void __launch_bounds__(512)
build_kernel() {
    __shared__ float es[16 * 33];
    __shared__ float ps[8 * 33];
    __shared__ float wls[512];
    __shared__ float sd[128];
    const int tid = threadIdx.x;
    const int u0 = blockIdx.x * 8, t0 = blockIdx.y * 16, bb = blockIdx.z;
    const int bIdx = (bb * 16 + blockIdx.y) * 16 + blockIdx.x;

    wls[tid] = g_wl[tid];
    if (tid < 128) sd[tid] = 0.f;

    const int reg  = tid & 3;
    const int lane = (tid >> 2) & 31;
    const int mt   = (tid >> 7) & 1;
    const int wml  = (tid >> 8) & 1;
    const int rbase = mt * 16 + (lane >> 2) + 8 * (reg & 1);
    float d2[2] = {0.f, 0.f};

    for (int kc = 0; kc < 16; kc++) {
        __syncthreads();
        {
            int row = tid >> 5, k = tid & 31;
            es[row * 33 + k] = g_e[(size_t)(bb * T_ + t0 + row) * JH_ + kc * 32 + k];
            if (tid < 256)
                ps[row * 33 + k] = g_p[(size_t)(bb * U_ + u0 + row) * JH_ + kc * 32 + k];
        }
        __syncthreads();
        float* dst = g_h + (size_t)(bIdx * 16 + kc) * 4096;
#pragma unroll
        for (int it = 0; it < 8; it++) {
            int wm = wml + 2 * (it & 1);
            int k8 = it >> 1;
            int row = wm * 32 + rbase;
            int kk = k8 * 8 + (lane & 3) + 4 * (reg >> 1);
            float v = fmaxf(es[(row >> 3) * 33 + kk] + ps[(row & 7) * 33 + kk], 0.f);
            d2[it & 1] += v * wls[kc * 32 + kk];
            unsigned uu; asm("cvt.rna.tf32.f32 %0,%1;" : "=r"(uu) : "f"(v));
            dst[it * 512 + tid] = __uint_as_float(uu);
        }
    }
    __syncthreads();
    atomicAdd(&sd[wml * 32 + rbase], d2[0]);
    atomicAdd(&sd[(wml + 2) * 32 + rbase], d2[1]);
    __syncthreads();
    if (tid < 128) g_d[bIdx * 128 + tid] = sd[tid];
}

// ---------------------------------------------------------------------------
// joint: M=128, N in 8 chunks of 128; 128 threads, 4 warps = 2(m) x 2(n),
// warp tile m64 x n64 (128 acc regs, deep ILP). 3-stage TMA pipeline,
// 32 KB/stage (A 16 KB + B 16 KB). 2 CTAs/SM.
// ---------------------------------------------------------------------------
#define S_M   24576
#define S_S   24704
#define S_PM  24832   /* [2][128] */
#define S_PS  25088   /* [2][128] */
#define S_LSE 25344
#define S_MB  25472   /* 6 mbarriers (48 B), 8B aligned */
#define SM_TOT 25488  /* floats = 101952 B */

__global__ void __launch_bounds__(128, 2)
joint_kernel(const float* __restrict__ b_out, float* __restrict__ out) {
    extern __shared__ float sm[];
    const int tid = threadIdx.x;
    const int lane = tid & 31, warp = tid >> 5;
    const int wm = warp & 1, wn = warp >> 1;      // 2 (m) x 2 (n)
    const int q = lane >> 2, cg = lane & 3;
    const int u0 = blockIdx.x * 8, t0 = blockIdx.y * 16, bb = blockIdx.z;
    const int bIdx = (bb * 16 + blockIdx.y) * 16 + blockIdx.x;

    const uint32_t smu = (uint32_t)__cvta_generic_to_shared(sm);
    const uint32_t mb_full = (uint32_t)__cvta_generic_to_shared(sm + S_MB);
    const uint32_t mb_emp  = mb_full + 24u;

    if (tid == 0) {
#pragma unroll
        for (int s = 0; s < 3; s++) {
            mbar_init(mb_full + 8u * s, 1);
            mbar_init(mb_emp + 8u * s, 4);    // one arrive per warp
        }
    }
    if (tid < 128) { sm[S_M + tid] = -1e30f; sm[S_S + tid] = 0.f; }
    __syncthreads();
    if (tid == 0) {
#pragma unroll
        for (int g0 = 0; g0 < 3; g0++) {
            uint32_t mb = mb_full + 8u * g0;
            mbar_expect_tx(mb, 32768u);
            bulk_g2s(smu + (uint32_t)g0 * 16384u,
                     g_h + (size_t)(bIdx * 16 + g0) * 4096, 16384u, mb);
            bulk_g2s(smu + 49152u + (uint32_t)g0 * 16384u,
                     g_wp + (size_t)g0 * 4096, 16384u, mb);
        }
    }

    // output row pointers: rows r = wm*64 + mt*16 + h*8 + q
    float* rowp[4][2];
#pragma unroll
    for (int mt = 0; mt < 4; mt++)
#pragma unroll
        for (int h = 0; h < 2; h++) {
            int r = wm * 64 + mt * 16 + h * 8 + q;
            int t = t0 + (r >> 3), u = u0 + (r & 7);
            rowp[mt][h] = out + (size_t)((bb * T_ + t) * U_ + u) * NC_;
        }

    const float4* A4 = (const float4*)sm + (wm * 4) * 32 + lane;         // + s*1024 + (k8*8+mt)*32
    const float4* B4 = (const float4*)sm + 3072 + (wn * 4) * 32 + lane;  // + s*1024 + (k8*8+jj)*32

    for (int nc = 0; nc < 8; nc++) {
        float acc[4][8][4];
#pragma unroll
        for (int mt = 0; mt < 4; mt++)
#pragma unroll
            for (int nt = 0; nt < 8; nt++)
#pragma unroll
                for (int i = 0; i < 4; i++) acc[mt][nt][i] = 0.f;

        for (int kc = 0; kc < 16; kc++) {
            const int g = nc * 16 + kc;
            const int gd = g / 3, s = g - gd * 3;
            mbar_wait(mb_full + 8u * s, gd & 1);

            const float4* As = A4 + s * 1024;
            const float4* Bs = B4 + s * 1024;
#pragma unroll
            for (int k8 = 0; k8 < 4; k8++) {
                float4 a[4], b[4];
#pragma unroll
                for (int mt = 0; mt < 4; mt++) a[mt] = As[(k8 * 8 + mt) * 32];
#pragma unroll
                for (int jj = 0; jj < 4; jj++) b[jj] = Bs[(k8 * 8 + jj) * 32];
#pragma unroll
                for (int mt = 0; mt < 4; mt++)
#pragma unroll
                    for (int jj = 0; jj < 4; jj++) {
                        mma_tf32(acc[mt][jj * 2],     a[mt], b[jj].x, b[jj].y);
                        mma_tf32(acc[mt][jj * 2 + 1], a[mt], b[jj].z, b[jj].w);
                    }
            }
            if (lane == 0) mbar_arrive(mb_emp + 8u * s);

            if (tid == 0) {
                int gp = g + 3;
                if (gp < 128) {
                    int gpd = gp / 3, sp = gp - gpd * 3;
                    mbar_wait(mb_emp + 8u * sp, (gpd + 1) & 1);
                    uint32_t mb = mb_full + 8u * sp;
                    mbar_expect_tx(mb, 32768u);
                    bulk_g2s(smu + (uint32_t)sp * 16384u,
                             g_h + (size_t)(bIdx * 16 + (gp & 15)) * 4096, 16384u, mb);
                    bulk_g2s(smu + 49152u + (uint32_t)sp * 16384u,
                             g_wp + (size_t)gp * 4096, 16384u, mb);
                }
            }
        }

        // ---- epilogue: bias, online stats, raw logit stores
        const int n0 = nc * 128;
#pragma unroll
        for (int nt = 0; nt < 8; nt++) {
            int off = n0 + wn * 64 + nt * 8 + 2 * cg;
            float b0 = __ldg(b_out + off);
            float b1 = __ldg(b_out + off + 1);
#pragma unroll
            for (int mt = 0; mt < 4; mt++) {
                acc[mt][nt][0] += b0;
                acc[mt][nt][1] += b1;
                acc[mt][nt][2] += b0;
                acc[mt][nt][3] += b1;
            }
        }

#pragma unroll
        for (int mt = 0; mt < 4; mt++)
#pragma unroll
            for (int h = 0; h < 2; h++) {
                float m = -1e30f;
#pragma unroll
                for (int nt = 0; nt < 8; nt++) {
                    m = fmaxf(m, acc[mt][nt][2 * h]);
                    m = fmaxf(m, acc[mt][nt][2 * h + 1]);
                }
                m = fmaxf(m, __shfl_xor_sync(0xffffffffu, m, 1));
                m = fmaxf(m, __shfl_xor_sync(0xffffffffu, m, 2));
                float s = 0.f;
#pragma unroll
                for (int nt = 0; nt < 8; nt++) {
                    s += __expf(acc[mt][nt][2 * h] - m);
                    s += __expf(acc[mt][nt][2 * h + 1] - m);
                }
                s += __shfl_xor_sync(0xffffffffu, s, 1);
                s += __shfl_xor_sync(0xffffffffu, s, 2);
                if (cg == 0) {
                    int r = wm * 64 + mt * 16 + h * 8 + q;
                    sm[S_PM + wn * 128 + r] = m;
                    sm[S_PS + wn * 128 + r] = s;
                }
            }

#pragma unroll
        for (int mt = 0; mt < 4; mt++)
#pragma unroll
            for (int h = 0; h < 2; h++) {
                float* rp = rowp[mt][h] + n0 + wn * 64;
#pragma unroll
                for (int nt = 0; nt < 8; nt++) {
                    rp[nt * 8 + 2 * cg]     = acc[mt][nt][2 * h];
                    rp[nt * 8 + 2 * cg + 1] = acc[mt][nt][2 * h + 1];
                }
            }

        __syncthreads();
        if (tid < 128) {
            float m = sm[S_M + tid], s = sm[S_S + tid];
#pragma unroll
            for (int w = 0; w < 2; w++) {
                float mc = sm[S_PM + w * 128 + tid];
                float sc = sm[S_PS + w * 128 + tid];
                float mn = fmaxf(m, mc);
                s = s * __expf(m - mn) + sc * __expf(mc - mn);
                m = mn;
            }
            sm[S_M + tid] = m;
            sm[S_S + tid] = s;
        }
        __syncthreads();
    }

    // ---- col 1024 + final LSE
    if (tid < 128) {
        int r = tid;
        float v = g_d[bIdx * 128 + r] + __ldg(b_out + 1024);
        float m = sm[S_M + r], s = sm[S_S + r];
        float mn = fmaxf(m, v);
        s = s * __expf(m - mn) + __expf(v - mn);
        float lse = mn + logf(s);
        sm[S_LSE + r] = lse;
        int t = t0 + (r >> 3), u = u0 + (r & 7);
        out[(size_t)((bb * T_ + t) * U_ + u) * NC_ + 1024] = v - lse;
    }
    __syncthreads();

    // ---- fixup: subtract LSE from cols 0..1023 (L2-hot, coalesced)
#pragma unroll 4
    for (int idx = tid; idx < 128 * 1024; idx += 128) {
        int r = idx >> 10, c = idx & 1023;
        int t = t0 + (r >> 3), u = u0 + (r & 7);
        out[(size_t)((bb * T_ + t) * U_ + u) * NC_ + c] -= sm[S_LSE + r];
    }
}

// ---------------------------------------------------------------------------
// launcher
// ---------------------------------------------------------------------------
extern "C" void kernel_launch(void* const* d_in, const int* in_sizes, int n_in,
                              void* d_out, int out_size) {
    const float* enc    = (const float*)d_in[0];
    const float* dec    = (const float*)d_in[1];
    const float* W_enc  = (const float*)d_in[2];
    const float* b_enc  = (const float*)d_in[3];
    const float* W_pred = (const float*)d_in[4];
    const float* b_pred = (const float*)d_in[5];
    const float* W_out  = (const float*)d_in[6];
    const float* b_out  = (const float*)d_in[7];
    float* out = (float*)d_out;

    void *pe = nullptr, *pp = nullptr;
    cudaGetSymbolAddress(&pe, g_e);
    cudaGetSymbolAddress(&pp, g_p);

    cudaFuncSetAttribute(joint_kernel, cudaFuncAttributeMaxDynamicSharedMemorySize,
                         SM_TOT * 4);

    pack_kernel<<<2048, 256>>>(W_out);
    proj_kernel<<<dim3(8, 16), 256>>>(enc, W_enc, b_enc, (float*)pe, T_, EH_);
    proj_kernel<<<dim3(8, 8), 256>>>(dec, W_pred, b_pred, (float*)pp, U_, PH_);

    dim3 grid(U_ / 8, T_ / 16, B_);   // (16, 16, 4) = 1024 blocks, 128 rows each
    build_kernel<<<grid, 512>>>();
    joint_kernel<<<grid, 128, SM_TOT * 4>>>(b_out, out);
}

// round 15
// speedup vs baseline: 2.1614x; 2.1614x over previous
#include <cuda_runtime.h>
#include <cuda_fp16.h>
#include <cstdint>

#define B_  4
#define T_  256
#define U_  128
#define EH_ 512
#define PH_ 320
#define JH_ 512
#define NC_ 1025

// ---------------------------------------------------------------------------
// scratch (no cudaMalloc allowed)
// ---------------------------------------------------------------------------
__device__ float  g_e[B_ * T_ * JH_];           // [b*T+t][512]
__device__ float  g_p[B_ * U_ * JH_];           // [b*U+u][512]
__device__ __half g_wp[JH_ * 1024];             // W f16: 64 chunks [k32 x n256] frag-packed (1 MB)
__device__ float  g_wl[JH_];                    // W col 1024 (fp32)
__device__ __half g_h[(size_t)1024 * 65536];    // H f16 frag-packed: 134 MB
__device__ float  g_d[1024 * 128];              // per-row col-1024 dots

// ---------------------------------------------------------------------------
// helpers
// ---------------------------------------------------------------------------
__device__ __forceinline__ void mma_f16(float* c, const float4& a, unsigned b0, unsigned b1) {
    const unsigned* au = reinterpret_cast<const unsigned*>(&a);
    asm volatile(
        "mma.sync.aligned.m16n8k16.row.col.f32.f16.f16.f32 "
        "{%0,%1,%2,%3},{%4,%5,%6,%7},{%8,%9},{%0,%1,%2,%3};\n"
        : "+f"(c[0]), "+f"(c[1]), "+f"(c[2]), "+f"(c[3])
        : "r"(au[0]), "r"(au[1]), "r"(au[2]), "r"(au[3]), "r"(b0), "r"(b1));
}
__device__ __forceinline__ void mbar_init(uint32_t mbar, uint32_t count) {
    asm volatile("mbarrier.init.shared.b64 [%0], %1;\n" :: "r"(mbar), "r"(count) : "memory");
}
__device__ __forceinline__ void mbar_expect_tx(uint32_t mbar, uint32_t bytes) {
    asm volatile("mbarrier.arrive.expect_tx.shared.b64 _, [%0], %1;\n"
                 :: "r"(mbar), "r"(bytes) : "memory");
}
__device__ __forceinline__ void mbar_arrive(uint32_t mbar) {
    asm volatile("mbarrier.arrive.release.cta.shared::cta.b64 _, [%0];\n"
                 :: "r"(mbar) : "memory");
}
__device__ __forceinline__ void bulk_g2s(uint32_t dst, const void* src, uint32_t bytes,
                                         uint32_t mbar) {
    asm volatile(
        "cp.async.bulk.shared::cluster.global.mbarrier::complete_tx::bytes "
        "[%0], [%1], %2, [%3];\n"
        :: "r"(dst), "l"(src), "r"(bytes), "r"(mbar) : "memory");
}
__device__ __forceinline__ void mbar_wait(uint32_t mbar, uint32_t parity) {
    uint32_t done;
    asm volatile(
        "{\n\t.reg .pred p;\n\t"
        "mbarrier.try_wait.parity.acquire.cta.shared::cta.b64 p, [%1], %2;\n\t"
        "selp.b32 %0, 1, 0, p;\n\t}"
        : "=r"(done) : "r"(mbar), "r"(parity) : "memory");
    if (!done) {
        asm volatile(
            "{\n\t.reg .pred P1;\n\t"
            "W_%=:\n\t"
            "mbarrier.try_wait.parity.acquire.cta.shared::cta.b64 P1, [%0], %1, 0x989680;\n\t"
            "@P1 bra.uni D_%=;\n\t"
            "bra.uni W_%=;\n\t"
            "D_%=:\n\t}"
            :: "r"(mbar), "r"(parity) : "memory");
    }
}

// ---------------------------------------------------------------------------
// projection: O[row][j] = sum_h X[b][h][t] * W[h][j] + bias[j]
// ---------------------------------------------------------------------------
__global__ void __launch_bounds__(256)
proj_kernel(const float* __restrict__ X, const float* __restrict__ W,
            const float* __restrict__ bias, float* __restrict__ O,
            int L, int H) {
    __shared__ float Xs[16][64];
    __shared__ float Ws[16][64];
    int tid = threadIdx.x;
    int tc = tid & 15, tr = tid >> 4;
    int j0 = blockIdx.x * 64;
    int row0 = blockIdx.y * 64;
    int b = row0 / L;
    int t0 = row0 % L;

    float acc[4][4];
#pragma unroll
    for (int i = 0; i < 4; i++)
#pragma unroll
        for (int j = 0; j < 4; j++) acc[i][j] = 0.f;

    for (int k0 = 0; k0 < H; k0 += 16) {
#pragma unroll
        for (int i = 0; i < 4; i++) {
            int idx = tid + i * 256;
            int ky = idx >> 6, xx = idx & 63;
            Xs[ky][xx] = X[(size_t)(b * H + k0 + ky) * L + t0 + xx];
            Ws[ky][xx] = W[(size_t)(k0 + ky) * JH_ + j0 + xx];
        }
        __syncthreads();
#pragma unroll
        for (int k = 0; k < 16; k++) {
            float a[4], w[4];
#pragma unroll
            for (int i = 0; i < 4; i++) { a[i] = Xs[k][tr * 4 + i]; w[i] = Ws[k][tc * 4 + i]; }
#pragma unroll
            for (int i = 0; i < 4; i++)
#pragma unroll
                for (int j = 0; j < 4; j++) acc[i][j] += a[i] * w[j];
        }
        __syncthreads();
    }
#pragma unroll
    for (int i = 0; i < 4; i++)
#pragma unroll
        for (int j = 0; j < 4; j++) {
            int col = j0 + tc * 4 + j;
            O[(size_t)(row0 + tr * 4 + i) * JH_ + col] = acc[i][j] + bias[col];
        }
}

// ---------------------------------------------------------------------------
// pack W_out (f16): 64 chunks (g = nc*16 + kc) of [k32 x n256], m16n8k16
// fragment order. uint32 index within chunk (4096 per chunk):
//   q bits: r[0:2) lane[2:7) p[7:11) ks[11:12)
//   tile nt = 2p + (r>>1); k_local = ks*16 + (r&1)*8 + (lane&3)*2 (+1 in hi half)
//   n_local = nt*8 + (lane>>2)
// ---------------------------------------------------------------------------
__global__ void pack_kernel(const float* __restrict__ W) {
    int d = blockIdx.x * 256 + threadIdx.x;   // uint32 index, total 262144
    if (d < JH_ * 512) {
        int q = d & 4095;
        int chunk = d >> 12;
        int kc = chunk & 15, nc = chunk >> 4;
        int r    = q & 3;
        int lane = (q >> 2) & 31;
        int p    = (q >> 7) & 15;
        int ks   = (q >> 11) & 1;
        int nt = 2 * p + (r >> 1);
        int kl = ks * 16 + (r & 1) * 8 + (lane & 3) * 2;
        int n  = nc * 256 + nt * 8 + (lane >> 2);
        int j  = kc * 32 + kl;
        __half2 hv = __floats2half2_rn(W[(size_t)j * NC_ + n],
                                       W[(size_t)(j + 1) * NC_ + n]);
        reinterpret_cast<uint32_t*>(g_wp)[d] = *reinterpret_cast<uint32_t*>(&hv);
    }
    if (d < JH_) g_wl[d] = W[(size_t)d * NC_ + 1024];
}

// ---------------------------------------------------------------------------
// build H (f16): per block 128 rows (16t x 8u), 16 chunks of [m128 x k32]
// fragment-packed for m16n8k16. uint32 index within chunk (2048):
//   idx bits: r[0:2) lane[2:7) mt8[7:10) ks[10:11)
//   row = mt8*16 + (lane>>2) + 8*(r&1); k = ks*16 + 8*(r>>1) + (lane&3)*2 (+1)
// Also folds col-1024 dot (fp32, pre-rounding) into g_d.
// ---------------------------------------------------------------------------
__global__ void __launch_bounds__(512)
build_kernel() {
    __shared__ float es[16 * 33];
    __shared__ float ps[8 * 33];
    __shared__ float wls[512];
    __shared__ float sd[128];
    const int tid = threadIdx.x;
    const int u0 = blockIdx.x * 8, t0 = blockIdx.y * 16, bb = blockIdx.z;
    const int bIdx = (bb * 16 + blockIdx.y) * 16 + blockIdx.x;

    wls[tid] = g_wl[tid];
    if (tid < 128) sd[tid] = 0.f;

    const int r4   = tid & 3;
    const int lane = (tid >> 2) & 31;
    const int hi   = tid >> 7;                     // 0..3
    const int rlow = (lane >> 2) + 8 * (r4 & 1);   // row within m16 tile
    float d2[2] = {0.f, 0.f};                      // rows hi*16+rlow, (hi+4)*16+rlow

    for (int kc = 0; kc < 16; kc++) {
        __syncthreads();
        {
            int row = tid >> 5, k = tid & 31;
            es[row * 33 + k] = g_e[(size_t)(bb * T_ + t0 + row) * JH_ + kc * 32 + k];
            if (tid < 256)
                ps[row * 33 + k] = g_p[(size_t)(bb * U_ + u0 + row) * JH_ + kc * 32 + k];
        }
        __syncthreads();
        uint32_t* dst = reinterpret_cast<uint32_t*>(g_h) + (size_t)(bIdx * 16 + kc) * 2048;
#pragma unroll
        for (int w32 = 0; w32 < 4; w32++) {
            int mt8 = (w32 & 1) * 4 + hi;
            int ks  = w32 >> 1;
            int row = mt8 * 16 + rlow;
            int k0  = ks * 16 + 8 * (r4 >> 1) + (lane & 3) * 2;
            float v0 = fmaxf(es[(row >> 3) * 33 + k0]     + ps[(row & 7) * 33 + k0],     0.f);
            float v1 = fmaxf(es[(row >> 3) * 33 + k0 + 1] + ps[(row & 7) * 33 + k0 + 1], 0.f);
            d2[w32 & 1] += v0 * wls[kc * 32 + k0] + v1 * wls[kc * 32 + k0 + 1];
            __half2 hv = __floats2half2_rn(v0, v1);
            dst[w32 * 512 + tid] = *reinterpret_cast<uint32_t*>(&hv);
        }
    }
    __syncthreads();
    atomicAdd(&sd[hi * 16 + rlow], d2[0]);
    atomicAdd(&sd[(hi + 4) * 16 + rlow], d2[1]);
    __syncthreads();
    if (tid < 128) g_d[bIdx * 128 + tid] = sd[tid];
}

// ---------------------------------------------------------------------------
// joint: f16 GEMM. M=128, N 4 chunks of 256, K 16 chunks of 32.
// 512 threads = 16 warps = 4(m) x 4(n); warp tile m32 x n64.
// 4-stage pipeline, 24 KB/stage (A 8 KB + B 16 KB), TMA bulk.
// smem bytes: A stages [0,32768), B stages [32768,98304); floats after.
// ---------------------------------------------------------------------------
#define S_M   24576
#define S_S   24704
#define S_PM  24832   /* [4][128] */
#define S_PS  25344   /* [4][128] */
#define S_LSE 25856
#define S_MB  25984   /* 8 mbarriers (64 B), 8B aligned */
#define SM_TOT 26000  /* floats = 104000 B */

__global__ void __launch_bounds__(512, 1)
joint_kernel(const float* __restrict__ b_out, float* __restrict__ out) {
    extern __shared__ float sm[];
    const int tid = threadIdx.x;
    const int lane = tid & 31, warp = tid >> 5;
    const int wm = warp & 3, wn = warp >> 2;      // 4 (m) x 4 (n)
    const int q = lane >> 2, cg = lane & 3;
    const int u0 = blockIdx.x * 8, t0 = blockIdx.y * 16, bb = blockIdx.z;
    const int bIdx = (bb * 16 + blockIdx.y) * 16 + blockIdx.x;

    const uint32_t smu = (uint32_t)__cvta_generic_to_shared(sm);
    const uint32_t mb_full = (uint32_t)__cvta_generic_to_shared(sm + S_MB);
    const uint32_t mb_emp  = mb_full + 32u;

    if (tid < 128) { sm[S_M + tid] = -1e30f; sm[S_S + tid] = 0.f; }
    if (tid == 0) {
#pragma unroll
        for (int s = 0; s < 4; s++) {
            mbar_init(mb_full + 8u * s, 1);
            mbar_init(mb_emp + 8u * s, 16);
        }
    }
    __syncthreads();
    if (tid == 0) {
#pragma unroll
        for (int g0 = 0; g0 < 4; g0++) {
            uint32_t mb = mb_full + 8u * g0;
            mbar_expect_tx(mb, 24576u);
            bulk_g2s(smu + (uint32_t)g0 * 8192u,
                     g_h + (size_t)(bIdx * 16 + g0) * 4096, 8192u, mb);
            bulk_g2s(smu + 32768u + (uint32_t)g0 * 16384u,
                     g_wp + (size_t)g0 * 8192, 16384u, mb);
        }
    }

    // output row pointers: rows r = wm*32 + mt*16 + h*8 + q
    float* rowp[2][2];
#pragma unroll
    for (int mt = 0; mt < 2; mt++)
#pragma unroll
        for (int h = 0; h < 2; h++) {
            int r = wm * 32 + mt * 16 + h * 8 + q;
            int t = t0 + (r >> 3), u = u0 + (r & 7);
            rowp[mt][h] = out + (size_t)((bb * T_ + t) * U_ + u) * NC_;
        }

    const float4* A4 = (const float4*)sm + lane;          // + s*512  + (ks*8 + wm*2 + mt)*32
    const float4* B4 = (const float4*)sm + 2048 + lane;   // + s*1024 + (ks*16 + wn*4 + pp)*32

    for (int nc = 0; nc < 4; nc++) {
        float acc[2][8][4];
#pragma unroll
        for (int mt = 0; mt < 2; mt++)
#pragma unroll
            for (int nt = 0; nt < 8; nt++)
#pragma unroll
                for (int i = 0; i < 4; i++) acc[mt][nt][i] = 0.f;

        for (int kc = 0; kc < 16; kc++) {
            const int g = nc * 16 + kc, s = g & 3;
            mbar_wait(mb_full + 8u * s, (g >> 2) & 1);

            const float4* As = A4 + s * 512;
            const float4* Bs = B4 + s * 1024;
#pragma unroll
            for (int ks = 0; ks < 2; ks++) {
                float4 a[2], bp[4];
#pragma unroll
                for (int mt = 0; mt < 2; mt++)
                    a[mt] = As[(ks * 8 + wm * 2 + mt) * 32];
#pragma unroll
                for (int pp = 0; pp < 4; pp++)
                    bp[pp] = Bs[(ks * 16 + wn * 4 + pp) * 32];
#pragma unroll
                for (int mt = 0; mt < 2; mt++)
#pragma unroll
                    for (int pp = 0; pp < 4; pp++) {
                        mma_f16(acc[mt][pp * 2], a[mt],
                                __float_as_uint(bp[pp].x), __float_as_uint(bp[pp].y));
                        mma_f16(acc[mt][pp * 2 + 1], a[mt],
                                __float_as_uint(bp[pp].z), __float_as_uint(bp[pp].w));
                    }
            }
            if (lane == 0) mbar_arrive(mb_emp + 8u * s);

            if (tid == 0) {
                int gp = g + 4;
                if (gp < 64) {
                    int sp = gp & 3;
                    mbar_wait(mb_emp + 8u * sp, ((gp >> 2) + 1) & 1);
                    uint32_t mb = mb_full + 8u * sp;
                    mbar_expect_tx(mb, 24576u);
                    bulk_g2s(smu + (uint32_t)sp * 8192u,
                             g_h + (size_t)(bIdx * 16 + (gp & 15)) * 4096, 8192u, mb);
                    bulk_g2s(smu + 32768u + (uint32_t)sp * 16384u,
                             g_wp + (size_t)gp * 8192, 16384u, mb);
                }
            }
        }

        // ---- epilogue: bias, online stats, raw logit stores
        const int n0 = nc * 256;
#pragma unroll
        for (int nt = 0; nt < 8; nt++) {
            int off = n0 + wn * 64 + nt * 8 + 2 * cg;
            float b0 = __ldg(b_out + off);
            float b1 = __ldg(b_out + off + 1);
#pragma unroll
            for (int mt = 0; mt < 2; mt++) {
                acc[mt][nt][0] += b0;
                acc[mt][nt][1] += b1;
                acc[mt][nt][2] += b0;
                acc[mt][nt][3] += b1;
            }
        }

#pragma unroll
        for (int mt = 0; mt < 2; mt++)
#pragma unroll
            for (int h = 0; h < 2; h++) {
                float m = -1e30f;
#pragma unroll
                for (int nt = 0; nt < 8; nt++) {
                    m = fmaxf(m, acc[mt][nt][2 * h]);
                    m = fmaxf(m, acc[mt][nt][2 * h + 1]);
                }
                m = fmaxf(m, __shfl_xor_sync(0xffffffffu, m, 1));
                m = fmaxf(m, __shfl_xor_sync(0xffffffffu, m, 2));
                float s = 0.f;
#pragma unroll
                for (int nt = 0; nt < 8; nt++) {
                    s += __expf(acc[mt][nt][2 * h] - m);
                    s += __expf(acc[mt][nt][2 * h + 1] - m);
                }
                s += __shfl_xor_sync(0xffffffffu, s, 1);
                s += __shfl_xor_sync(0xffffffffu, s, 2);
                if (cg == 0) {
                    int r = wm * 32 + mt * 16 + h * 8 + q;
                    sm[S_PM + wn * 128 + r] = m;
                    sm[S_PS + wn * 128 + r] = s;
                }
            }

#pragma unroll
        for (int mt = 0; mt < 2; mt++)
#pragma unroll
            for (int h = 0; h < 2; h++) {
                float* rp = rowp[mt][h] + n0 + wn * 64;
#pragma unroll
                for (int nt = 0; nt < 8; nt++) {
                    rp[nt * 8 + 2 * cg]     = acc[mt][nt][2 * h];
                    rp[nt * 8 + 2 * cg + 1] = acc[mt][nt][2 * h + 1];
                }
            }

        __syncthreads();
        if (tid < 128) {
            float m = sm[S_M + tid], s = sm[S_S + tid];
#pragma unroll
            for (int w = 0; w < 4; w++) {
                float mc = sm[S_PM + w * 128 + tid];
                float sc = sm[S_PS + w * 128 + tid];
                float mn = fmaxf(m, mc);
                s = s * __expf(m - mn) + sc * __expf(mc - mn);
                m = mn;
            }
            sm[S_M + tid] = m;
            sm[S_S + tid] = s;
        }
        __syncthreads();
    }

    // ---- col 1024 + final LSE
    if (tid < 128) {
        int r = tid;
        float v = g_d[bIdx * 128 + r] + __ldg(b_out + 1024);
        float m = sm[S_M + r], s = sm[S_S + r];
        float mn = fmaxf(m, v);
        s = s * __expf(m - mn) + __expf(v - mn);
        float lse = mn + logf(s);
        sm[S_LSE + r] = lse;
        int t = t0 + (r >> 3), u = u0 + (r & 7);
        out[(size_t)((bb * T_ + t) * U_ + u) * NC_ + 1024] = v - lse;
    }
    __syncthreads();

    // ---- fixup: subtract LSE from cols 0..1023 (L2-hot, coalesced)
#pragma unroll 4
    for (int idx = tid; idx < 128 * 1024; idx += 512) {
        int r = idx >> 10, c = idx & 1023;
        int t = t0 + (r >> 3), u = u0 + (r & 7);
        out[(size_t)((bb * T_ + t) * U_ + u) * NC_ + c] -= sm[S_LSE + r];
    }
}

// ---------------------------------------------------------------------------
// launcher
// ---------------------------------------------------------------------------
extern "C" void kernel_launch(void* const* d_in, const int* in_sizes, int n_in,
                              void* d_out, int out_size) {
    const float* enc    = (const float*)d_in[0];
    const float* dec    = (const float*)d_in[1];
    const float* W_enc  = (const float*)d_in[2];
    const float* b_enc  = (const float*)d_in[3];
    const float* W_pred = (const float*)d_in[4];
    const float* b_pred = (const float*)d_in[5];
    const float* W_out  = (const float*)d_in[6];
    const float* b_out  = (const float*)d_in[7];
    float* out = (float*)d_out;

    void *pe = nullptr, *pp = nullptr;
    cudaGetSymbolAddress(&pe, g_e);
    cudaGetSymbolAddress(&pp, g_p);

    cudaFuncSetAttribute(joint_kernel, cudaFuncAttributeMaxDynamicSharedMemorySize,
                         SM_TOT * 4);

    pack_kernel<<<1024, 256>>>(W_out);
    proj_kernel<<<dim3(8, 16), 256>>>(enc, W_enc, b_enc, (float*)pe, T_, EH_);
    proj_kernel<<<dim3(8, 8), 256>>>(dec, W_pred, b_pred, (float*)pp, U_, PH_);

    dim3 grid(U_ / 8, T_ / 16, B_);   // (16, 16, 4) = 1024 blocks, 128 rows each
    build_kernel<<<grid, 512>>>();
    joint_kernel<<<grid, 512, SM_TOT * 4>>>(b_out, out);
}